// round 15
// baseline (speedup 1.0000x reference)
#include <cuda_runtime.h>
#include <cuda_fp16.h>
#include <cstdint>

#define B 16
#define C 256
#define O_CH 256
#define H 128
#define W 128
#define G 32
#define CG 8
#define OG 8
#define HW (H*W)

#define RSTRIP 8
#define TROWS (RSTRIP+2)   // 10 staged rows
#define TC 132             // cols: 0=left pad, 1..128 px, 129=right pad
#define SLAB (130*132)     // uint4 entries per (b,g)

__device__ float d_mean[B*C];
__device__ float d_inv[B*C];
__device__ float d_comb[B*O_CH*CG*9];
__device__ float d_bias2[B*O_CH];
__device__ float d_part[B*G*4*16];
__device__ uint4 d_xh[B*G*SLAB];        // fp16 x, pixel-major [row][col][8ch]

__device__ __forceinline__ uint32_t pkh2(float a, float b) {
    __half2 h = __floats2half2_rn(a, b);
    return *reinterpret_cast<uint32_t*>(&h);
}
__device__ __forceinline__ uint32_t smem_u32(const void* p) {
    uint32_t a;
    asm("{ .reg .u64 t; cvta.to.shared.u64 t, %1; cvt.u32.u64 %0, t; }" : "=r"(a) : "l"(p));
    return a;
}
__device__ __forceinline__ uint32_t SW(uint32_t a16) { return a16 ^ ((a16 >> 3) & 7u); }
__device__ __forceinline__ void sts128(uint32_t addr, uint32_t a, uint32_t b, uint32_t c, uint32_t d) {
    asm volatile("st.shared.v4.b32 [%0], {%1,%2,%3,%4};" :: "r"(addr), "r"(a), "r"(b), "r"(c), "r"(d) : "memory");
}

// ---------------------------------------------------------------------------
// Kernel 1: fp16 transpose-convert + partial stats. 1 px/iter, low regs,
// high occupancy (8 CTAs/SM) for DRAM MLP.
// ---------------------------------------------------------------------------
__global__ __launch_bounds__(256, 8) void transform_kernel(const float* __restrict__ x) {
    __shared__ float rs[8][16];
    int chunk = blockIdx.x & 3;
    int bg    = blockIdx.x >> 2;
    int b = bg >> 5, g = bg & 31;
    int tid = threadIdx.x, lane = tid & 31, wid = tid >> 5;

    const float* xb = x + (size_t)(b*C + g*CG) * HW + (size_t)chunk * 32 * W;
    uint4* slab = d_xh + (size_t)bg * SLAB + (size_t)(chunk*32 + 1) * TC;

    float s[CG], ss[CG];
    #pragma unroll
    for (int c = 0; c < CG; c++) { s[c] = 0.f; ss[c] = 0.f; }

    #pragma unroll
    for (int i = 0; i < 16; i++) {
        int px = tid + i * 256;
        float v[CG];
        #pragma unroll
        for (int c = 0; c < CG; c++) v[c] = xb[(size_t)c*HW + px];
        #pragma unroll
        for (int c = 0; c < CG; c++) {
            s[c] += v[c];
            ss[c] = fmaf(v[c], v[c], ss[c]);
        }
        int r = px >> 7, cc = px & 127;
        slab[r*TC + cc + 1] = make_uint4(pkh2(v[0], v[1]), pkh2(v[2], v[3]),
                                         pkh2(v[4], v[5]), pkh2(v[6], v[7]));
    }

    #pragma unroll
    for (int c = 0; c < CG; c++) {
        #pragma unroll
        for (int o = 16; o > 0; o >>= 1) {
            s[c]  += __shfl_down_sync(0xffffffffu, s[c],  o);
            ss[c] += __shfl_down_sync(0xffffffffu, ss[c], o);
        }
    }
    if (lane == 0) {
        #pragma unroll
        for (int c = 0; c < CG; c++) { rs[wid][c] = s[c]; rs[wid][8 + c] = ss[c]; }
    }
    __syncthreads();
    if (tid < 16) {
        float S = 0.f;
        #pragma unroll
        for (int w = 0; w < 8; w++) S += rs[w][tid];
        d_part[(size_t)blockIdx.x * 16 + tid] = S;
    }
}

// ---------------------------------------------------------------------------
// Kernel 2: finalize stats + borders + fold 1x1+norm into weights/bias.
// ---------------------------------------------------------------------------
__global__ __launch_bounds__(256) void finalize_kernel(const float* __restrict__ dw,
                                                       const float* __restrict__ pw,
                                                       const float* __restrict__ biases) {
    __shared__ float mean8[CG], inv8[CG];
    __shared__ float red[OG*72];
    int bg = blockIdx.x;
    int b = bg >> 5, g = bg & 31;
    int tid = threadIdx.x;

    if (tid < CG) {
        float S = 0.f, SS = 0.f;
        #pragma unroll
        for (int c = 0; c < 4; c++) {
            S  += d_part[(size_t)(bg*4 + c)*16 + tid];
            SS += d_part[(size_t)(bg*4 + c)*16 + 8 + tid];
        }
        float mean = S * (1.0f / HW);
        float var  = (SS - S * mean) * (1.0f / (HW - 1));
        var = fmaxf(var, 0.0f);
        float iv = 1.0f / (sqrtf(var) + 1e-7f);
        d_mean[b*C + g*CG + tid] = mean;
        d_inv [b*C + g*CG + tid] = iv;
        mean8[tid] = mean;
        inv8[tid]  = iv;
    }
    __syncthreads();

    uint4 mp = make_uint4(pkh2(mean8[0], mean8[1]), pkh2(mean8[2], mean8[3]),
                          pkh2(mean8[4], mean8[5]), pkh2(mean8[6], mean8[7]));
    uint4* slab = d_xh + (size_t)bg * SLAB;
    for (int i = tid; i < TC; i += 256) { slab[i] = mp; slab[129*TC + i] = mp; }
    for (int r = 1 + tid; r <= 128; r += 256) { slab[r*TC] = mp; slab[r*TC + 129] = mp; }

    for (int idx = tid; idx < OG*72; idx += 256) {
        int o = idx / 72, it = idx % 72, i = it / 9, tap = it % 9;
        const float* pwp = pw + (size_t)(b*O_CH + g*OG + o) * OG;
        float acc = 0.f;
        #pragma unroll
        for (int ip = 0; ip < 8; ip++)
            acc += pwp[ip] * dw[(((size_t)b*O_CH + (g*OG + ip))*CG + i)*9 + tap];
        float wp = acc * inv8[i];
        d_comb[(size_t)(b*O_CH + g*OG + o)*72 + it] = wp;
        red[idx] = wp * mean8[i];
    }
    __syncthreads();
    if (tid < OG) {
        float sm = 0.f;
        #pragma unroll
        for (int k = 0; k < 72; k++) sm += red[tid*72 + k];
        d_bias2[b*O_CH + g*OG + tid] = biases[b*O_CH + g*OG + tid] - sm;
    }
}

// ---------------------------------------------------------------------------
// Kernel 3: grouped 3x3 conv via HMMA + ldmatrix (R8 inner structure),
// RSTRIP=8, 256 threads, reg-capped for 6 CTAs/SM (48 warps latency cover).
// ---------------------------------------------------------------------------
__global__ __launch_bounds__(256, 6) void conv_kernel(float* __restrict__ out) {
    __shared__ __align__(16) __half tile[TROWS*TC*CG];   // 21120 B
    __shared__ float wsm[OG*72];

    int b  = blockIdx.z;
    int g  = blockIdx.y;
    int r0 = blockIdx.x * RSTRIP;
    int tid  = threadIdx.x;
    int lane = tid & 31;
    int wi   = tid >> 5;          // warp -> output row r0 + wi
    uint32_t sb = smem_u32(tile);

    {
        const float* cb = d_comb + (size_t)(b*O_CH + g*OG) * 72;
        for (int idx = tid; idx < OG*72; idx += 256) wsm[idx] = cb[idx];
    }
    {
        const uint4* src = d_xh + (size_t)(b*G + g) * SLAB + (size_t)r0 * TC;
        #pragma unroll
        for (int k = 0; k < 6; k++) {
            int e = tid + k * 256;
            if (e < TROWS*TC) {
                uint4 v = src[e];
                sts128(sb + SW((uint32_t)e)*16u, v.x, v.y, v.z, v.w);
            }
        }
    }
    __syncthreads();

    int gid = lane >> 2;
    int tg  = lane & 3;
    uint32_t bf[9];
    {
        const float* wn = wsm + gid * 72 + (tg * 2) * 9;
        #pragma unroll
        for (int j = 0; j < 4; j++) {
            bf[2*j + 0] = pkh2(wn[2*j],     wn[9 + 2*j]);
            bf[2*j + 1] = pkh2(wn[2*j + 1], wn[9 + 2*j + 1]);
        }
        bf[8] = pkh2(wn[8], wn[17]);
    }

    int q  = lane >> 3;
    int l8 = lane & 7;
    int base_j[4], base_8;
    #pragma unroll
    for (int j = 0; j < 4; j++) {
        int t = 2*j + (q >> 1);
        base_j[j] = (wi + t/3)*TC + (q & 1)*8 + l8 + (t % 3);
    }
    base_8 = (wi + 2)*TC + (q & 1)*8 + l8 + 2;

    float bia0 = d_bias2[b*O_CH + g*OG + tg*2];
    float bia1 = d_bias2[b*O_CH + g*OG + tg*2 + 1];

    int hrow = r0 + wi;
    float* obase = out + (size_t)(b*O_CH + g*OG + tg*2) * HW + (size_t)hrow * W;

    #pragma unroll
    for (int ws = 0; ws < 8; ws++) {
        int w16 = ws * 16;
        float d0 = 0.f, d1 = 0.f, d2 = 0.f, d3 = 0.f;

        #pragma unroll
        for (int j = 0; j < 4; j++) {
            uint32_t addr = sb + SW((uint32_t)(base_j[j] + w16))*16u;
            uint32_t a0, a1, a2, a3;
            asm volatile("ldmatrix.sync.aligned.m8n8.x4.shared.b16 {%0,%1,%2,%3}, [%4];"
                         : "=r"(a0), "=r"(a1), "=r"(a2), "=r"(a3) : "r"(addr));
            asm volatile(
                "mma.sync.aligned.m16n8k16.row.col.f32.f16.f16.f32 "
                "{%0,%1,%2,%3},{%4,%5,%6,%7},{%8,%9},{%0,%1,%2,%3};"
                : "+f"(d0), "+f"(d1), "+f"(d2), "+f"(d3)
                : "r"(a0), "r"(a1), "r"(a2), "r"(a3),
                  "r"(bf[2*j]), "r"(bf[2*j + 1]));
        }
        {
            uint32_t addr = sb + SW((uint32_t)(base_8 + w16))*16u;
            uint32_t a0, a1;
            asm volatile("ldmatrix.sync.aligned.m8n8.x2.shared.b16 {%0,%1}, [%2];"
                         : "=r"(a0), "=r"(a1) : "r"(addr));
            asm volatile(
                "mma.sync.aligned.m16n8k8.row.col.f32.f16.f16.f32 "
                "{%0,%1,%2,%3},{%4,%5},{%6},{%0,%1,%2,%3};"
                : "+f"(d0), "+f"(d1), "+f"(d2), "+f"(d3)
                : "r"(a0), "r"(a1), "r"(bf[8]));
        }

        float* ob = obase + w16 + gid;
        ob[0]      = d0 + bia0;
        ob[HW]     = d1 + bia1;
        ob[8]      = d2 + bia0;
        ob[HW + 8] = d3 + bia1;
    }
}

// ---------------------------------------------------------------------------
extern "C" void kernel_launch(void* const* d_in, const int* in_sizes, int n_in,
                              void* d_out, int out_size) {
    const float* x      = (const float*)d_in[0];
    const float* dw     = (const float*)d_in[1];
    const float* pw     = (const float*)d_in[2];
    const float* biases = (const float*)d_in[3];
    float* out = (float*)d_out;

    transform_kernel<<<B*G*4, 256>>>(x);
    finalize_kernel<<<B*G, 256>>>(dw, pw, biases);
    conv_kernel<<<dim3(H/RSTRIP, G, B), 256>>>(out);
}

// round 16
// speedup vs baseline: 1.0113x; 1.0113x over previous
#include <cuda_runtime.h>
#include <cuda_fp16.h>
#include <cstdint>

#define B 16
#define C 256
#define O_CH 256
#define H 128
#define W 128
#define G 32
#define CG 8
#define OG 8
#define HW (H*W)

#define RSTRIP 8
#define TROWS (RSTRIP+2)   // 10 staged rows
#define TC 132             // cols: 0=left pad, 1..128 px, 129=right pad
#define SLAB (130*132)     // uint4 entries per (b,g)

__device__ float d_mean[B*C];
__device__ float d_inv[B*C];
__device__ float d_comb[B*O_CH*CG*9];
__device__ float d_bias2[B*O_CH];
__device__ float d_part[B*G*4*16];
__device__ uint4 d_xh[B*G*SLAB];        // fp16 x, pixel-major [row][col][8ch]

__device__ __forceinline__ uint32_t pkh2(float a, float b) {
    __half2 h = __floats2half2_rn(a, b);
    return *reinterpret_cast<uint32_t*>(&h);
}
__device__ __forceinline__ uint32_t smem_u32(const void* p) {
    uint32_t a;
    asm("{ .reg .u64 t; cvta.to.shared.u64 t, %1; cvt.u32.u64 %0, t; }" : "=r"(a) : "l"(p));
    return a;
}
__device__ __forceinline__ uint32_t SW(uint32_t a16) { return a16 ^ ((a16 >> 3) & 7u); }
__device__ __forceinline__ void sts128(uint32_t addr, uint32_t a, uint32_t b, uint32_t c, uint32_t d) {
    asm volatile("st.shared.v4.b32 [%0], {%1,%2,%3,%4};" :: "r"(addr), "r"(a), "r"(b), "r"(c), "r"(d) : "memory");
}

// ---------------------------------------------------------------------------
// Kernel 1: fp16 transpose-convert + partial stats (R14-proven: 2 px/iter,
// 16 independent loads in flight per thread).
// ---------------------------------------------------------------------------
__global__ __launch_bounds__(256) void transform_kernel(const float* __restrict__ x) {
    __shared__ float rs[8][16];
    int chunk = blockIdx.x & 3;
    int bg    = blockIdx.x >> 2;
    int b = bg >> 5, g = bg & 31;
    int tid = threadIdx.x, lane = tid & 31, wid = tid >> 5;

    const float* xb = x + (size_t)(b*C + g*CG) * HW + (size_t)chunk * 32 * W;
    uint4* slab = d_xh + (size_t)bg * SLAB + (size_t)(chunk*32 + 1) * TC;

    float s[CG], ss[CG];
    #pragma unroll
    for (int c = 0; c < CG; c++) { s[c] = 0.f; ss[c] = 0.f; }

    #pragma unroll
    for (int i = 0; i < 8; i++) {
        int pxA = tid + (2*i)   * 256;
        int pxB = tid + (2*i+1) * 256;
        float vA[CG], vB[CG];
        #pragma unroll
        for (int c = 0; c < CG; c++) {
            vA[c] = xb[(size_t)c*HW + pxA];
            vB[c] = xb[(size_t)c*HW + pxB];
        }
        #pragma unroll
        for (int c = 0; c < CG; c++) {
            s[c] += vA[c] + vB[c];
            ss[c] = fmaf(vA[c], vA[c], ss[c]);
            ss[c] = fmaf(vB[c], vB[c], ss[c]);
        }
        int rA = pxA >> 7, cA = pxA & 127;
        int rB = pxB >> 7, cB = pxB & 127;
        slab[rA*TC + cA + 1] = make_uint4(pkh2(vA[0], vA[1]), pkh2(vA[2], vA[3]),
                                          pkh2(vA[4], vA[5]), pkh2(vA[6], vA[7]));
        slab[rB*TC + cB + 1] = make_uint4(pkh2(vB[0], vB[1]), pkh2(vB[2], vB[3]),
                                          pkh2(vB[4], vB[5]), pkh2(vB[6], vB[7]));
    }

    #pragma unroll
    for (int c = 0; c < CG; c++) {
        #pragma unroll
        for (int o = 16; o > 0; o >>= 1) {
            s[c]  += __shfl_down_sync(0xffffffffu, s[c],  o);
            ss[c] += __shfl_down_sync(0xffffffffu, ss[c], o);
        }
    }
    if (lane == 0) {
        #pragma unroll
        for (int c = 0; c < CG; c++) { rs[wid][c] = s[c]; rs[wid][8 + c] = ss[c]; }
    }
    __syncthreads();
    if (tid < 16) {
        float S = 0.f;
        #pragma unroll
        for (int w = 0; w < 8; w++) S += rs[w][tid];
        d_part[(size_t)blockIdx.x * 16 + tid] = S;
    }
}

// ---------------------------------------------------------------------------
// Kernel 2: finalize stats + borders + fold 1x1+norm into weights/bias.
// ---------------------------------------------------------------------------
__global__ __launch_bounds__(256) void finalize_kernel(const float* __restrict__ dw,
                                                       const float* __restrict__ pw,
                                                       const float* __restrict__ biases) {
    __shared__ float mean8[CG], inv8[CG];
    __shared__ float red[OG*72];
    int bg = blockIdx.x;
    int b = bg >> 5, g = bg & 31;
    int tid = threadIdx.x;

    if (tid < CG) {
        float S = 0.f, SS = 0.f;
        #pragma unroll
        for (int c = 0; c < 4; c++) {
            S  += d_part[(size_t)(bg*4 + c)*16 + tid];
            SS += d_part[(size_t)(bg*4 + c)*16 + 8 + tid];
        }
        float mean = S * (1.0f / HW);
        float var  = (SS - S * mean) * (1.0f / (HW - 1));
        var = fmaxf(var, 0.0f);
        float iv = 1.0f / (sqrtf(var) + 1e-7f);
        d_mean[b*C + g*CG + tid] = mean;
        d_inv [b*C + g*CG + tid] = iv;
        mean8[tid] = mean;
        inv8[tid]  = iv;
    }
    __syncthreads();

    uint4 mp = make_uint4(pkh2(mean8[0], mean8[1]), pkh2(mean8[2], mean8[3]),
                          pkh2(mean8[4], mean8[5]), pkh2(mean8[6], mean8[7]));
    uint4* slab = d_xh + (size_t)bg * SLAB;
    for (int i = tid; i < TC; i += 256) { slab[i] = mp; slab[129*TC + i] = mp; }
    for (int r = 1 + tid; r <= 128; r += 256) { slab[r*TC] = mp; slab[r*TC + 129] = mp; }

    for (int idx = tid; idx < OG*72; idx += 256) {
        int o = idx / 72, it = idx % 72, i = it / 9, tap = it % 9;
        const float* pwp = pw + (size_t)(b*O_CH + g*OG + o) * OG;
        float acc = 0.f;
        #pragma unroll
        for (int ip = 0; ip < 8; ip++)
            acc += pwp[ip] * dw[(((size_t)b*O_CH + (g*OG + ip))*CG + i)*9 + tap];
        float wp = acc * inv8[i];
        d_comb[(size_t)(b*O_CH + g*OG + o)*72 + it] = wp;
        red[idx] = wp * mean8[i];
    }
    __syncthreads();
    if (tid < OG) {
        float sm = 0.f;
        #pragma unroll
        for (int k = 0; k < 72; k++) sm += red[tid*72 + k];
        d_bias2[b*O_CH + g*OG + tid] = biases[b*O_CH + g*OG + tid] - sm;
    }
}

// ---------------------------------------------------------------------------
// Kernel 3: grouped 3x3 conv via HMMA + ldmatrix (R8 inner structure),
// RSTRIP=8, 256 threads, reg-capped for 6 CTAs/SM (48 warps latency cover).
// ---------------------------------------------------------------------------
__global__ __launch_bounds__(256, 6) void conv_kernel(float* __restrict__ out) {
    __shared__ __align__(16) __half tile[TROWS*TC*CG];   // 21120 B
    __shared__ float wsm[OG*72];

    int b  = blockIdx.z;
    int g  = blockIdx.y;
    int r0 = blockIdx.x * RSTRIP;
    int tid  = threadIdx.x;
    int lane = tid & 31;
    int wi   = tid >> 5;          // warp -> output row r0 + wi
    uint32_t sb = smem_u32(tile);

    {
        const float* cb = d_comb + (size_t)(b*O_CH + g*OG) * 72;
        for (int idx = tid; idx < OG*72; idx += 256) wsm[idx] = cb[idx];
    }
    {
        const uint4* src = d_xh + (size_t)(b*G + g) * SLAB + (size_t)r0 * TC;
        #pragma unroll
        for (int k = 0; k < 6; k++) {
            int e = tid + k * 256;
            if (e < TROWS*TC) {
                uint4 v = src[e];
                sts128(sb + SW((uint32_t)e)*16u, v.x, v.y, v.z, v.w);
            }
        }
    }
    __syncthreads();

    int gid = lane >> 2;
    int tg  = lane & 3;
    uint32_t bf[9];
    {
        const float* wn = wsm + gid * 72 + (tg * 2) * 9;
        #pragma unroll
        for (int j = 0; j < 4; j++) {
            bf[2*j + 0] = pkh2(wn[2*j],     wn[9 + 2*j]);
            bf[2*j + 1] = pkh2(wn[2*j + 1], wn[9 + 2*j + 1]);
        }
        bf[8] = pkh2(wn[8], wn[17]);
    }

    int q  = lane >> 3;
    int l8 = lane & 7;
    int base_j[4], base_8;
    #pragma unroll
    for (int j = 0; j < 4; j++) {
        int t = 2*j + (q >> 1);
        base_j[j] = (wi + t/3)*TC + (q & 1)*8 + l8 + (t % 3);
    }
    base_8 = (wi + 2)*TC + (q & 1)*8 + l8 + 2;

    float bia0 = d_bias2[b*O_CH + g*OG + tg*2];
    float bia1 = d_bias2[b*O_CH + g*OG + tg*2 + 1];

    int hrow = r0 + wi;
    float* obase = out + (size_t)(b*O_CH + g*OG + tg*2) * HW + (size_t)hrow * W;

    #pragma unroll
    for (int ws = 0; ws < 8; ws++) {
        int w16 = ws * 16;
        float d0 = 0.f, d1 = 0.f, d2 = 0.f, d3 = 0.f;

        #pragma unroll
        for (int j = 0; j < 4; j++) {
            uint32_t addr = sb + SW((uint32_t)(base_j[j] + w16))*16u;
            uint32_t a0, a1, a2, a3;
            asm volatile("ldmatrix.sync.aligned.m8n8.x4.shared.b16 {%0,%1,%2,%3}, [%4];"
                         : "=r"(a0), "=r"(a1), "=r"(a2), "=r"(a3) : "r"(addr));
            asm volatile(
                "mma.sync.aligned.m16n8k16.row.col.f32.f16.f16.f32 "
                "{%0,%1,%2,%3},{%4,%5,%6,%7},{%8,%9},{%0,%1,%2,%3};"
                : "+f"(d0), "+f"(d1), "+f"(d2), "+f"(d3)
                : "r"(a0), "r"(a1), "r"(a2), "r"(a3),
                  "r"(bf[2*j]), "r"(bf[2*j + 1]));
        }
        {
            uint32_t addr = sb + SW((uint32_t)(base_8 + w16))*16u;
            uint32_t a0, a1;
            asm volatile("ldmatrix.sync.aligned.m8n8.x2.shared.b16 {%0,%1}, [%2];"
                         : "=r"(a0), "=r"(a1) : "r"(addr));
            asm volatile(
                "mma.sync.aligned.m16n8k8.row.col.f32.f16.f16.f32 "
                "{%0,%1,%2,%3},{%4,%5},{%6},{%0,%1,%2,%3};"
                : "+f"(d0), "+f"(d1), "+f"(d2), "+f"(d3)
                : "r"(a0), "r"(a1), "r"(bf[8]));
        }

        float* ob = obase + w16 + gid;
        ob[0]      = d0 + bia0;
        ob[HW]     = d1 + bia1;
        ob[8]      = d2 + bia0;
        ob[HW + 8] = d3 + bia1;
    }
}

// ---------------------------------------------------------------------------
extern "C" void kernel_launch(void* const* d_in, const int* in_sizes, int n_in,
                              void* d_out, int out_size) {
    const float* x      = (const float*)d_in[0];
    const float* dw     = (const float*)d_in[1];
    const float* pw     = (const float*)d_in[2];
    const float* biases = (const float*)d_in[3];
    float* out = (float*)d_out;

    transform_kernel<<<B*G*4, 256>>>(x);
    finalize_kernel<<<B*G, 256>>>(dw, pw, biases);
    conv_kernel<<<dim3(H/RSTRIP, G, B), 256>>>(out);
}

// round 17
// speedup vs baseline: 1.0313x; 1.0198x over previous
#include <cuda_runtime.h>
#include <cuda_fp16.h>
#include <cstdint>

#define B 16
#define C 256
#define O_CH 256
#define H 128
#define W 128
#define G 32
#define CG 8
#define OG 8
#define HW (H*W)

#define RSTRIP 8
#define TROWS (RSTRIP+2)   // 10 staged rows
#define TC 132             // cols: 0=left pad, 1..128 px, 129=right pad
#define SLAB (130*132)     // uint4 entries per (b,g)

__device__ float d_mean[B*C];
__device__ float d_inv[B*C];
__device__ float d_comb[B*O_CH*CG*9];
__device__ float d_bias2[B*O_CH];
__device__ float d_part[B*G*4*16];
__device__ uint4 d_xh[B*G*SLAB];        // fp16 x, pixel-major [row][col][8ch]

__device__ __forceinline__ uint32_t pkh2(float a, float b) {
    __half2 h = __floats2half2_rn(a, b);
    return *reinterpret_cast<uint32_t*>(&h);
}
__device__ __forceinline__ uint32_t smem_u32(const void* p) {
    uint32_t a;
    asm("{ .reg .u64 t; cvta.to.shared.u64 t, %1; cvt.u32.u64 %0, t; }" : "=r"(a) : "l"(p));
    return a;
}
__device__ __forceinline__ uint32_t SW(uint32_t a16) { return a16 ^ ((a16 >> 3) & 7u); }
__device__ __forceinline__ void sts128(uint32_t addr, uint32_t a, uint32_t b, uint32_t c, uint32_t d) {
    asm volatile("st.shared.v4.b32 [%0], {%1,%2,%3,%4};" :: "r"(addr), "r"(a), "r"(b), "r"(c), "r"(d) : "memory");
}

// ---------------------------------------------------------------------------
// Kernel 1: fp16 transpose-convert + partial stats.
// Thread owns 4 consecutive px x 8 ch: 8x LDG.128 in flight (1KB/thread),
// 4 contiguous uint4 stores. 4 iters cover the 32-row chunk.
// ---------------------------------------------------------------------------
__global__ __launch_bounds__(256, 4) void transform_kernel(const float* __restrict__ x) {
    __shared__ float rs[8][16];
    int chunk = blockIdx.x & 3;
    int bg    = blockIdx.x >> 2;
    int b = bg >> 5, g = bg & 31;
    int tid = threadIdx.x, lane = tid & 31, wid = tid >> 5;

    const float* xb = x + (size_t)(b*C + g*CG) * HW + (size_t)chunk * 32 * W;
    uint4* slab = d_xh + (size_t)bg * SLAB + (size_t)(chunk*32 + 1) * TC;

    float s[CG], ss[CG];
    #pragma unroll
    for (int c = 0; c < CG; c++) { s[c] = 0.f; ss[c] = 0.f; }

    #pragma unroll
    for (int it = 0; it < 4; it++) {
        int p0 = tid * 4 + it * 1024;        // multiple of 4 -> float4 aligned
        int row = p0 >> 7, col = p0 & 127;
        float4 v4[CG];
        #pragma unroll
        for (int c = 0; c < CG; c++)
            v4[c] = *(const float4*)(xb + (size_t)c*HW + p0);
        #pragma unroll
        for (int c = 0; c < CG; c++) {
            s[c] += v4[c].x + v4[c].y + v4[c].z + v4[c].w;
            ss[c] = fmaf(v4[c].x, v4[c].x, ss[c]);
            ss[c] = fmaf(v4[c].y, v4[c].y, ss[c]);
            ss[c] = fmaf(v4[c].z, v4[c].z, ss[c]);
            ss[c] = fmaf(v4[c].w, v4[c].w, ss[c]);
        }
        // repack: 4 pixel packets, each [8ch] fp16 = uint4
        const float* vf = (const float*)v4;   // vf[c*4 + k]
        uint4* dst = &slab[row*TC + col + 1];
        #pragma unroll
        for (int k = 0; k < 4; k++) {
            dst[k] = make_uint4(pkh2(vf[0*4+k], vf[1*4+k]),
                                pkh2(vf[2*4+k], vf[3*4+k]),
                                pkh2(vf[4*4+k], vf[5*4+k]),
                                pkh2(vf[6*4+k], vf[7*4+k]));
        }
    }

    #pragma unroll
    for (int c = 0; c < CG; c++) {
        #pragma unroll
        for (int o = 16; o > 0; o >>= 1) {
            s[c]  += __shfl_down_sync(0xffffffffu, s[c],  o);
            ss[c] += __shfl_down_sync(0xffffffffu, ss[c], o);
        }
    }
    if (lane == 0) {
        #pragma unroll
        for (int c = 0; c < CG; c++) { rs[wid][c] = s[c]; rs[wid][8 + c] = ss[c]; }
    }
    __syncthreads();
    if (tid < 16) {
        float S = 0.f;
        #pragma unroll
        for (int w = 0; w < 8; w++) S += rs[w][tid];
        d_part[(size_t)blockIdx.x * 16 + tid] = S;
    }
}

// ---------------------------------------------------------------------------
// Kernel 2: finalize stats + borders + fold 1x1+norm into weights/bias.
// ---------------------------------------------------------------------------
__global__ __launch_bounds__(256) void finalize_kernel(const float* __restrict__ dw,
                                                       const float* __restrict__ pw,
                                                       const float* __restrict__ biases) {
    __shared__ float mean8[CG], inv8[CG];
    __shared__ float red[OG*72];
    int bg = blockIdx.x;
    int b = bg >> 5, g = bg & 31;
    int tid = threadIdx.x;

    if (tid < CG) {
        float S = 0.f, SS = 0.f;
        #pragma unroll
        for (int c = 0; c < 4; c++) {
            S  += d_part[(size_t)(bg*4 + c)*16 + tid];
            SS += d_part[(size_t)(bg*4 + c)*16 + 8 + tid];
        }
        float mean = S * (1.0f / HW);
        float var  = (SS - S * mean) * (1.0f / (HW - 1));
        var = fmaxf(var, 0.0f);
        float iv = 1.0f / (sqrtf(var) + 1e-7f);
        d_mean[b*C + g*CG + tid] = mean;
        d_inv [b*C + g*CG + tid] = iv;
        mean8[tid] = mean;
        inv8[tid]  = iv;
    }
    __syncthreads();

    uint4 mp = make_uint4(pkh2(mean8[0], mean8[1]), pkh2(mean8[2], mean8[3]),
                          pkh2(mean8[4], mean8[5]), pkh2(mean8[6], mean8[7]));
    uint4* slab = d_xh + (size_t)bg * SLAB;
    for (int i = tid; i < TC; i += 256) { slab[i] = mp; slab[129*TC + i] = mp; }
    for (int r = 1 + tid; r <= 128; r += 256) { slab[r*TC] = mp; slab[r*TC + 129] = mp; }

    for (int idx = tid; idx < OG*72; idx += 256) {
        int o = idx / 72, it = idx % 72, i = it / 9, tap = it % 9;
        const float* pwp = pw + (size_t)(b*O_CH + g*OG + o) * OG;
        float acc = 0.f;
        #pragma unroll
        for (int ip = 0; ip < 8; ip++)
            acc += pwp[ip] * dw[(((size_t)b*O_CH + (g*OG + ip))*CG + i)*9 + tap];
        float wp = acc * inv8[i];
        d_comb[(size_t)(b*O_CH + g*OG + o)*72 + it] = wp;
        red[idx] = wp * mean8[i];
    }
    __syncthreads();
    if (tid < OG) {
        float sm = 0.f;
        #pragma unroll
        for (int k = 0; k < 72; k++) sm += red[tid*72 + k];
        d_bias2[b*O_CH + g*OG + tid] = biases[b*O_CH + g*OG + tid] - sm;
    }
}

// ---------------------------------------------------------------------------
// Kernel 3: grouped 3x3 conv via HMMA + ldmatrix (R8 inner structure),
// RSTRIP=8, 256 threads, reg-capped for 6 CTAs/SM.
// ---------------------------------------------------------------------------
__global__ __launch_bounds__(256, 6) void conv_kernel(float* __restrict__ out) {
    __shared__ __align__(16) __half tile[TROWS*TC*CG];   // 21120 B
    __shared__ float wsm[OG*72];

    int b  = blockIdx.z;
    int g  = blockIdx.y;
    int r0 = blockIdx.x * RSTRIP;
    int tid  = threadIdx.x;
    int lane = tid & 31;
    int wi   = tid >> 5;          // warp -> output row r0 + wi
    uint32_t sb = smem_u32(tile);

    {
        const float* cb = d_comb + (size_t)(b*O_CH + g*OG) * 72;
        for (int idx = tid; idx < OG*72; idx += 256) wsm[idx] = cb[idx];
    }
    {
        const uint4* src = d_xh + (size_t)(b*G + g) * SLAB + (size_t)r0 * TC;
        #pragma unroll
        for (int k = 0; k < 6; k++) {
            int e = tid + k * 256;
            if (e < TROWS*TC) {
                uint4 v = src[e];
                sts128(sb + SW((uint32_t)e)*16u, v.x, v.y, v.z, v.w);
            }
        }
    }
    __syncthreads();

    int gid = lane >> 2;
    int tg  = lane & 3;
    uint32_t bf[9];
    {
        const float* wn = wsm + gid * 72 + (tg * 2) * 9;
        #pragma unroll
        for (int j = 0; j < 4; j++) {
            bf[2*j + 0] = pkh2(wn[2*j],     wn[9 + 2*j]);
            bf[2*j + 1] = pkh2(wn[2*j + 1], wn[9 + 2*j + 1]);
        }
        bf[8] = pkh2(wn[8], wn[17]);
    }

    int q  = lane >> 3;
    int l8 = lane & 7;
    int base_j[4], base_8;
    #pragma unroll
    for (int j = 0; j < 4; j++) {
        int t = 2*j + (q >> 1);
        base_j[j] = (wi + t/3)*TC + (q & 1)*8 + l8 + (t % 3);
    }
    base_8 = (wi + 2)*TC + (q & 1)*8 + l8 + 2;

    float bia0 = d_bias2[b*O_CH + g*OG + tg*2];
    float bia1 = d_bias2[b*O_CH + g*OG + tg*2 + 1];

    int hrow = r0 + wi;
    float* obase = out + (size_t)(b*O_CH + g*OG + tg*2) * HW + (size_t)hrow * W;

    #pragma unroll
    for (int ws = 0; ws < 8; ws++) {
        int w16 = ws * 16;
        float d0 = 0.f, d1 = 0.f, d2 = 0.f, d3 = 0.f;

        #pragma unroll
        for (int j = 0; j < 4; j++) {
            uint32_t addr = sb + SW((uint32_t)(base_j[j] + w16))*16u;
            uint32_t a0, a1, a2, a3;
            asm volatile("ldmatrix.sync.aligned.m8n8.x4.shared.b16 {%0,%1,%2,%3}, [%4];"
                         : "=r"(a0), "=r"(a1), "=r"(a2), "=r"(a3) : "r"(addr));
            asm volatile(
                "mma.sync.aligned.m16n8k16.row.col.f32.f16.f16.f32 "
                "{%0,%1,%2,%3},{%4,%5,%6,%7},{%8,%9},{%0,%1,%2,%3};"
                : "+f"(d0), "+f"(d1), "+f"(d2), "+f"(d3)
                : "r"(a0), "r"(a1), "r"(a2), "r"(a3),
                  "r"(bf[2*j]), "r"(bf[2*j + 1]));
        }
        {
            uint32_t addr = sb + SW((uint32_t)(base_8 + w16))*16u;
            uint32_t a0, a1;
            asm volatile("ldmatrix.sync.aligned.m8n8.x2.shared.b16 {%0,%1}, [%2];"
                         : "=r"(a0), "=r"(a1) : "r"(addr));
            asm volatile(
                "mma.sync.aligned.m16n8k8.row.col.f32.f16.f16.f32 "
                "{%0,%1,%2,%3},{%4,%5},{%6},{%0,%1,%2,%3};"
                : "+f"(d0), "+f"(d1), "+f"(d2), "+f"(d3)
                : "r"(a0), "r"(a1), "r"(bf[8]));
        }

        float* ob = obase + w16 + gid;
        ob[0]      = d0 + bia0;
        ob[HW]     = d1 + bia1;
        ob[8]      = d2 + bia0;
        ob[HW + 8] = d3 + bia1;
    }
}

// ---------------------------------------------------------------------------
extern "C" void kernel_launch(void* const* d_in, const int* in_sizes, int n_in,
                              void* d_out, int out_size) {
    const float* x      = (const float*)d_in[0];
    const float* dw     = (const float*)d_in[1];
    const float* pw     = (const float*)d_in[2];
    const float* biases = (const float*)d_in[3];
    float* out = (float*)d_out;

    transform_kernel<<<B*G*4, 256>>>(x);
    finalize_kernel<<<B*G, 256>>>(dw, pw, biases);
    conv_kernel<<<dim3(H/RSTRIP, G, B), 256>>>(out);
}